// round 2
// baseline (speedup 1.0000x reference)
#include <cuda_runtime.h>
#include <math.h>

#define HIDDEN 768
#define INTER 3072
#define HEADS 12
#define HEAD_DIM 256
#define BATCH 8
#define SEQ 4096
#define ROWS (BATCH*SEQ)

// ---------------- scratch (static device globals; no allocation) ----------------
__device__ float g_qacc[INTER];            // q pre-scale accumulator (init = bq)
__device__ float g_q[INTER];               // scaled q [h][d]
__device__ float g_wk[HIDDEN*HEADS];       // folded key weights [c][h]
__device__ float g_qbk[HEADS];             // q . bk per head
__device__ float g_logits[BATCH*HEADS*SEQ];
__device__ float g_p[BATCH*HEADS*HIDDEN];  // attn-pooled hidden
__device__ float g_ctx[BATCH*INTER];
__device__ float g_out[BATCH*HIDDEN];      // pre-LN output

// ---------------- K0: init g_p = 0, g_qacc = bq ----------------
__global__ void k0_init(const float* __restrict__ bq) {
    int i = blockIdx.x * 256 + threadIdx.x;        // grid 288*256 = 73728 = |g_p|
    g_p[i] = 0.0f;
    if (i < INTER) g_qacc[i] = bq[i];
}

// ---------------- K1: q partial dots (atomic), grid (12h x 8 cchunk) ----------------
__global__ void k1_qpart(const float* __restrict__ pq, const float* __restrict__ Wq) {
    int h = blockIdx.x >> 3;
    int c0 = (blockIdx.x & 7) * 96;
    __shared__ float sq[96];
    if (threadIdx.x < 96) sq[threadIdx.x] = pq[c0 + threadIdx.x];
    __syncthreads();
    int col = h * HEAD_DIM + threadIdx.x;
    float acc = 0.0f;
#pragma unroll 8
    for (int c = 0; c < 96; c++)
        acc += sq[c] * Wq[(size_t)(c0 + c) * INTER + col];
    atomicAdd(&g_qacc[col], acc);
}

// ---------------- K1b: scale q by scale * softplus(per_dim_scale) ----------------
__global__ void k1b_qscale(const float* __restrict__ pds) {
    int i = blockIdx.x * 256 + threadIdx.x;        // grid 12*256 = 3072
    int d = threadIdx.x;                            // HEAD_DIM == 256
    float x = pds[d];
    float sp = (x > 20.0f) ? x : log1pf(expf(x));
    const float scale = 1.442695041f / 16.0f;       // r_softplus_0 / sqrt(HEAD_DIM)
    g_q[i] = g_qacc[i] * scale * sp;
}

// ---------------- K2: fold wk[c][h] = Wk[c, h*256+d] . q[h,:] ; qbk ----------------
__global__ void k2_fold(const float* __restrict__ Wk, const float* __restrict__ bk) {
    int wid = threadIdx.x >> 5;                     // head (block = 384 = 12 warps)
    int lane = threadIdx.x & 31;
    if (blockIdx.x < HIDDEN) {
        int c = blockIdx.x;
        const float* wrow = Wk + (size_t)c * INTER + wid * HEAD_DIM;
        const float* qrow = g_q + wid * HEAD_DIM;
        float s = 0.0f;
#pragma unroll
        for (int j = lane; j < HEAD_DIM; j += 32) s += wrow[j] * qrow[j];
#pragma unroll
        for (int o = 16; o; o >>= 1) s += __shfl_xor_sync(0xffffffffu, s, o);
        if (!lane) g_wk[c * HEADS + wid] = s;
    } else {                                        // block 768: qbk
        const float* qrow = g_q + wid * HEAD_DIM;
        const float* brow = bk + wid * HEAD_DIM;
        float s = 0.0f;
        for (int j = lane; j < HEAD_DIM; j += 32) s += qrow[j] * brow[j];
#pragma unroll
        for (int o = 16; o; o >>= 1) s += __shfl_xor_sync(0xffffffffu, s, o);
        if (!lane) g_qbk[wid] = s;
    }
}

// ---------------- K3: logits[b,h,s] = hidden row . wk  (big streaming pass A) ----
__global__ __launch_bounds__(256) void k3_logits(const float* __restrict__ hidden) {
    __shared__ float s_wk[HIDDEN * HEADS];          // 36 KB
    __shared__ float s_qbk[HEADS];
    for (int i = threadIdx.x; i < HIDDEN * HEADS; i += 256) s_wk[i] = g_wk[i];
    if (threadIdx.x < HEADS) s_qbk[threadIdx.x] = g_qbk[threadIdx.x];
    __syncthreads();

    int t = blockIdx.x * 256 + threadIdx.x;         // grid 512*256; 4 threads/row
    int row = t >> 2;
    int sub = t & 3;
    const float4* h4 = (const float4*)(hidden + (size_t)row * HIDDEN + sub * 192);

    float acc[HEADS];
#pragma unroll
    for (int h = 0; h < HEADS; h++) acc[h] = 0.0f;

    int cbase = sub * 192;
#pragma unroll 4
    for (int i = 0; i < 48; i++) {
        float4 hv = h4[i];
        const float* w = s_wk + (cbase + i * 4) * HEADS;
        float v0 = hv.x, v1 = hv.y, v2 = hv.z, v3 = hv.w;
#pragma unroll
        for (int h = 0; h < HEADS; h++) acc[h] += v0 * w[h];
#pragma unroll
        for (int h = 0; h < HEADS; h++) acc[h] += v1 * w[HEADS + h];
#pragma unroll
        for (int h = 0; h < HEADS; h++) acc[h] += v2 * w[2 * HEADS + h];
#pragma unroll
        for (int h = 0; h < HEADS; h++) acc[h] += v3 * w[3 * HEADS + h];
    }
#pragma unroll
    for (int h = 0; h < HEADS; h++) {
        acc[h] += __shfl_xor_sync(0xffffffffu, acc[h], 1);
        acc[h] += __shfl_xor_sync(0xffffffffu, acc[h], 2);
    }
    if (sub == 0) {
        int b = row >> 12;
        int s = row & (SEQ - 1);
#pragma unroll
        for (int h = 0; h < HEADS; h++)
            g_logits[((size_t)(b * HEADS + h)) * SEQ + s] = acc[h] + s_qbk[h];
    }
}

// ---------------- K4: softmax over s per (b,h) -> attn output; also init g_ctx/g_out
__global__ __launch_bounds__(256) void k4_softmax(float* __restrict__ out_attn,
                                                  const float* __restrict__ bv,
                                                  const float* __restrict__ bp) {
    int gid = blockIdx.x * 256 + threadIdx.x;       // grid 96*256 = 24576 = |g_ctx|
    g_ctx[gid] = bv[gid % INTER];
    if (gid < BATCH * HIDDEN) g_out[gid] = bp[gid % HIDDEN];

    __shared__ float sv[SEQ];                       // 16 KB
    __shared__ float red[8];
    __shared__ float sbc;
    int bh = blockIdx.x;
    int tid = threadIdx.x, lane = tid & 31, wid = tid >> 5;
    const float* lg = g_logits + (size_t)bh * SEQ;

    float mx = -3.4e38f;
    for (int i = tid; i < SEQ; i += 256) { float v = lg[i]; sv[i] = v; mx = fmaxf(mx, v); }
#pragma unroll
    for (int o = 16; o; o >>= 1) mx = fmaxf(mx, __shfl_xor_sync(0xffffffffu, mx, o));
    if (!lane) red[wid] = mx;
    __syncthreads();
    if (tid == 0) { float m = red[0]; for (int w = 1; w < 8; w++) m = fmaxf(m, red[w]); sbc = m; }
    __syncthreads();
    float m = sbc;

    float sum = 0.0f;
    for (int i = tid; i < SEQ; i += 256) { float e = __expf(sv[i] - m); sv[i] = e; sum += e; }
#pragma unroll
    for (int o = 16; o; o >>= 1) sum += __shfl_xor_sync(0xffffffffu, sum, o);
    if (!lane) red[wid] = sum;
    __syncthreads();
    if (tid == 0) { float s = 0; for (int w = 0; w < 8; w++) s += red[w]; sbc = 1.0f / s; }
    __syncthreads();
    float inv = sbc;
    for (int i = tid; i < SEQ; i += 256) out_attn[(size_t)bh * SEQ + i] = sv[i] * inv;
}

// ---------------- K5: p[b,h,c] = sum_s attn * hidden (big streaming pass C) ------
__global__ __launch_bounds__(192) void k5_pool(const float* __restrict__ hidden,
                                               const float* __restrict__ attn) {
    __shared__ float s_a[64 * HEADS];               // [r][h], 3 KB
    int b = blockIdx.x >> 6;                        // grid = 8*64 blocks, 64 rows each
    int s0 = (blockIdx.x & 63) * 64;
    for (int i = threadIdx.x; i < 64 * HEADS; i += 192) {
        int h = i >> 6, r = i & 63;
        s_a[r * HEADS + h] = attn[((size_t)(b * HEADS + h)) * SEQ + s0 + r];
    }
    __syncthreads();

    int c0 = threadIdx.x * 4;                       // 192*4 = 768
    const float4* hp = (const float4*)(hidden + ((size_t)b * SEQ + s0) * HIDDEN + c0);

    float acc[HEADS * 4];
#pragma unroll
    for (int i = 0; i < HEADS * 4; i++) acc[i] = 0.0f;

#pragma unroll 2
    for (int r = 0; r < 64; r++) {
        float4 hv = hp[(size_t)r * (HIDDEN / 4)];
        const float* ar = s_a + r * HEADS;
#pragma unroll
        for (int h = 0; h < HEADS; h++) {
            float a = ar[h];
            acc[h * 4 + 0] += a * hv.x;
            acc[h * 4 + 1] += a * hv.y;
            acc[h * 4 + 2] += a * hv.z;
            acc[h * 4 + 3] += a * hv.w;
        }
    }
    float* pd = g_p + (size_t)b * HEADS * HIDDEN;
#pragma unroll
    for (int h = 0; h < HEADS; h++)
#pragma unroll
        for (int j = 0; j < 4; j++)
            atomicAdd(&pd[h * HIDDEN + c0 + j], acc[h * 4 + j]);
}

// ---------------- K6a: ctx[b, h*256+d] = p[b,h,:].Wv col + bv (atomic over c) ----
__global__ __launch_bounds__(256) void k6a_ctx(const float* __restrict__ Wv) {
    int h = blockIdx.x >> 4;                        // grid 12*16
    int c0 = (blockIdx.x & 15) * 48;
    __shared__ float sp[BATCH][48];
    for (int i = threadIdx.x; i < BATCH * 48; i += 256) {
        int b = i / 48, c = i % 48;
        sp[b][c] = g_p[(size_t)(b * HEADS + h) * HIDDEN + c0 + c];
    }
    __syncthreads();
    int col = h * HEAD_DIM + threadIdx.x;
    float acc[BATCH];
#pragma unroll
    for (int b = 0; b < BATCH; b++) acc[b] = 0.0f;
#pragma unroll 4
    for (int c = 0; c < 48; c++) {
        float w = Wv[(size_t)(c0 + c) * INTER + col];
#pragma unroll
        for (int b = 0; b < BATCH; b++) acc[b] += sp[b][c] * w;
    }
#pragma unroll
    for (int b = 0; b < BATCH; b++) atomicAdd(&g_ctx[b * INTER + col], acc[b]);
}

// ---------------- K6b: out[b,j] = ctx[b,:].Wp col + bp (atomic over i) -----------
__global__ __launch_bounds__(256) void k6b_out(const float* __restrict__ Wp) {
    int ic = blockIdx.x / 3;                        // grid 48*3
    int jt = blockIdx.x % 3;
    int i0 = ic * 64;
    __shared__ float sc[BATCH][64];
    for (int i = threadIdx.x; i < BATCH * 64; i += 256) {
        int b = i / 64, ii = i % 64;
        sc[b][ii] = g_ctx[b * INTER + i0 + ii];
    }
    __syncthreads();
    int j = jt * 256 + threadIdx.x;
    float acc[BATCH];
#pragma unroll
    for (int b = 0; b < BATCH; b++) acc[b] = 0.0f;
#pragma unroll 4
    for (int ii = 0; ii < 64; ii++) {
        float w = Wp[(size_t)(i0 + ii) * HIDDEN + j];
#pragma unroll
        for (int b = 0; b < BATCH; b++) acc[b] += sc[b][ii] * w;
    }
#pragma unroll
    for (int b = 0; b < BATCH; b++) atomicAdd(&g_out[b * HIDDEN + j], acc[b]);
}

// ---------------- K7: layernorm per batch row -> pooled output -------------------
__global__ __launch_bounds__(256) void k7_ln(float* __restrict__ pooled,
                                             const float* __restrict__ lnw,
                                             const float* __restrict__ lnb) {
    int b = blockIdx.x, tid = threadIdx.x, lane = tid & 31, wid = tid >> 5;
    __shared__ float sx[HIDDEN];
    __shared__ float red[8];
    __shared__ float sm, sr;
    float loc = 0.0f;
    for (int i = tid; i < HIDDEN; i += 256) { float x = g_out[b * HIDDEN + i]; sx[i] = x; loc += x; }
#pragma unroll
    for (int o = 16; o; o >>= 1) loc += __shfl_xor_sync(0xffffffffu, loc, o);
    if (!lane) red[wid] = loc;
    __syncthreads();
    if (tid == 0) { float s = 0; for (int w = 0; w < 8; w++) s += red[w]; sm = s / HIDDEN; }
    __syncthreads();
    float mean = sm;
    loc = 0.0f;
    for (int i = tid; i < HIDDEN; i += 256) { float d = sx[i] - mean; loc += d * d; }
#pragma unroll
    for (int o = 16; o; o >>= 1) loc += __shfl_xor_sync(0xffffffffu, loc, o);
    if (!lane) red[wid] = loc;
    __syncthreads();
    if (tid == 0) { float s = 0; for (int w = 0; w < 8; w++) s += red[w]; sr = rsqrtf(s / HIDDEN + 1e-6f); }
    __syncthreads();
    float rstd = sr;
    for (int i = tid; i < HIDDEN; i += 256)
        pooled[b * HIDDEN + i] = (sx[i] - mean) * rstd * (lnw[i] + 1.0f) + lnb[i];
}

// ---------------- launch -----------------------------------------------------------
extern "C" void kernel_launch(void* const* d_in, const int* in_sizes, int n_in,
                              void* d_out, int out_size) {
    const float* hidden = (const float*)d_in[0];
    const float* pq     = (const float*)d_in[1];
    const float* Wq     = (const float*)d_in[2];
    const float* bq     = (const float*)d_in[3];
    const float* Wk     = (const float*)d_in[4];
    const float* bk     = (const float*)d_in[5];
    const float* Wv     = (const float*)d_in[6];
    const float* bv     = (const float*)d_in[7];
    const float* Wp     = (const float*)d_in[8];
    const float* bp     = (const float*)d_in[9];
    const float* pds    = (const float*)d_in[10];
    const float* lnw    = (const float*)d_in[11];
    const float* lnb    = (const float*)d_in[12];

    float* pooled   = (float*)d_out;                       // [8,1,768]
    float* out_attn = (float*)d_out + BATCH * HIDDEN;      // [8,12,1,4096]

    k0_init   <<<288, 256>>>(bq);
    k1_qpart  <<<96, 256>>>(pq, Wq);
    k1b_qscale<<<12, 256>>>(pds);
    k2_fold   <<<769, 384>>>(Wk, bk);
    k3_logits <<<512, 256>>>(hidden);
    k4_softmax<<<96, 256>>>(out_attn, bv, bp);
    k5_pool   <<<512, 192>>>(hidden, out_attn);
    k6a_ctx   <<<192, 256>>>(Wv);
    k6b_out   <<<144, 256>>>(Wp);
    k7_ln     <<<8, 256>>>(pooled, lnw, lnb);
}